// round 15
// baseline (speedup 1.0000x reference)
#include <cuda_runtime.h>
#include <cuda_fp16.h>
#include <math.h>
#include <stdint.h>

// Problem constants
#define BZ 4
#define SZ 2048
#define DD 768
#define HH 3072
#define EE 8
#define NTOK (BZ*SZ)          // 8192
#define NENT (NTOK*2)         // 16384
#define CAP  1536
#define ROWS_MAX (EE*CAP)     // 12288

// ---------------- device scratch (126 MB, under proven 189 MB bound) --------
__device__ int   g_topk_e[NENT];
__device__ float g_topk_p[NENT];
__device__ int   g_rows[ROWS_MAX];
__device__ int   g_cnt[EE];
__device__ int   g_slot[NENT];
__device__ float g_gate[NENT];
__device__ __half g_xh [(size_t)NTOK * DD];       // 12.6 MB (fp16 of x)
__device__ __half g_Hhi[(size_t)ROWS_MAX * HH];   // 75.5 MB (fp16 hi-plane of H)
__device__ float  g_Ybuf[(size_t)ROWS_MAX * DD];  // 37.7 MB

// ---------------- PTX helpers -----------------------------------------------
__device__ __forceinline__ uint32_t smem_u32(const void* p) {
    uint32_t a;
    asm("{ .reg .u64 t; cvta.to.shared.u64 t, %1; cvt.u32.u64 %0, t; }" : "=r"(a) : "l"(p));
    return a;
}
#define CPA16(dst, src) \
    asm volatile("cp.async.cg.shared.global [%0], [%1], 16;" :: "r"(dst), "l"(src))
#define CP_COMMIT() asm volatile("cp.async.commit_group;" ::: "memory")
#define CP_WAIT0()  asm volatile("cp.async.wait_group 0;" ::: "memory")

__device__ __forceinline__ void ldsm4(uint32_t& r0, uint32_t& r1, uint32_t& r2, uint32_t& r3,
                                      uint32_t addr) {
    asm volatile("ldmatrix.sync.aligned.m8n8.x4.shared.b16 {%0,%1,%2,%3}, [%4];"
                 : "=r"(r0), "=r"(r1), "=r"(r2), "=r"(r3) : "r"(addr));
}
__device__ __forceinline__ void ldsm4t(uint32_t& r0, uint32_t& r1, uint32_t& r2, uint32_t& r3,
                                       uint32_t addr) {
    asm volatile("ldmatrix.sync.aligned.m8n8.x4.trans.shared.b16 {%0,%1,%2,%3}, [%4];"
                 : "=r"(r0), "=r"(r1), "=r"(r2), "=r"(r3) : "r"(addr));
}
__device__ __forceinline__ void mma16816(float& c0, float& c1, float& c2, float& c3,
                                         uint32_t a0, uint32_t a1, uint32_t a2, uint32_t a3,
                                         uint32_t b0, uint32_t b1) {
    asm volatile("mma.sync.aligned.m16n8k16.row.col.f32.f16.f16.f32 "
                 "{%0,%1,%2,%3}, {%4,%5,%6,%7}, {%8,%9}, {%0,%1,%2,%3};"
                 : "+f"(c0), "+f"(c1), "+f"(c2), "+f"(c3)
                 : "r"(a0), "r"(a1), "r"(a2), "r"(a3), "r"(b0), "r"(b1));
}
__device__ __forceinline__ uint32_t cvt2h(float f0, float f1) {
    __half2 h = __floats2half2_rn(f0, f1);
    return *reinterpret_cast<uint32_t*>(&h);
}
__device__ __forceinline__ void split2h(float f0, float f1, uint32_t& hi, uint32_t& lo) {
    __half h0 = __float2half_rn(f0), h1 = __float2half_rn(f1);
    __half l0 = __float2half_rn(f0 - __half2float(h0));
    __half l1 = __float2half_rn(f1 - __half2float(h1));
    hi = (uint32_t)*(unsigned short*)&h0 | ((uint32_t)*(unsigned short*)&h1 << 16);
    lo = (uint32_t)*(unsigned short*)&l0 | ((uint32_t)*(unsigned short*)&l1 << 16);
}

// ---------------- pre-pass: x -> fp16 ----------------------------------------
__global__ void cvt_x_kernel(const float* __restrict__ x) {
    int i = blockIdx.x * blockDim.x + threadIdx.x;   // float4 index
    float4 v = reinterpret_cast<const float4*>(x)[i];
    uint2 q;
    q.x = cvt2h(v.x, v.y);
    q.y = cvt2h(v.z, v.w);
    *reinterpret_cast<uint2*>(&g_xh[i * 4]) = q;
}

// ---------------- router -----------------------------------------------------
__global__ void router_kernel(const float* __restrict__ x,
                              const float* __restrict__ Wr) {
    int warp = threadIdx.x >> 5;
    int lane = threadIdx.x & 31;
    int t = blockIdx.x * 8 + warp;
    if (t >= NTOK) return;
    const float* xr = x + (size_t)t * DD;
    float acc[EE];
#pragma unroll
    for (int e = 0; e < EE; e++) acc[e] = 0.f;
    for (int i = lane; i < DD; i += 32) {
        float xv = xr[i];
        const float4* wr4 = reinterpret_cast<const float4*>(Wr + i * EE);
        float4 w0 = wr4[0], w1 = wr4[1];
        acc[0] += xv * w0.x; acc[1] += xv * w0.y;
        acc[2] += xv * w0.z; acc[3] += xv * w0.w;
        acc[4] += xv * w1.x; acc[5] += xv * w1.y;
        acc[6] += xv * w1.z; acc[7] += xv * w1.w;
    }
#pragma unroll
    for (int e = 0; e < EE; e++)
#pragma unroll
        for (int o = 16; o > 0; o >>= 1)
            acc[e] += __shfl_xor_sync(0xffffffffu, acc[e], o);
    if (lane == 0) {
        float m = acc[0];
#pragma unroll
        for (int e = 1; e < EE; e++) m = fmaxf(m, acc[e]);
        float p[EE]; float s = 0.f;
#pragma unroll
        for (int e = 0; e < EE; e++) { p[e] = expf(acc[e] - m); s += p[e]; }
        float inv = 1.f / s;
#pragma unroll
        for (int e = 0; e < EE; e++) p[e] *= inv;
        int i0 = 0;
#pragma unroll
        for (int e = 1; e < EE; e++) if (p[e] > p[i0]) i0 = e;
        int i1 = -1;
#pragma unroll
        for (int e = 0; e < EE; e++) {
            if (e == i0) continue;
            if (i1 < 0 || p[e] > p[i1]) i1 = e;
        }
        float ps = 1.f / (p[i0] + p[i1]);
        g_topk_e[2 * t + 0] = i0; g_topk_p[2 * t + 0] = p[i0] * ps;
        g_topk_e[2 * t + 1] = i1; g_topk_p[2 * t + 1] = p[i1] * ps;
    }
}

// ---------------- capacity assignment (exact flat-order) ---------------------
#define ATH 512
#define EPT (NENT / ATH)
__global__ void assign_kernel() {
    __shared__ int sh[EE][ATH];
    int t = threadIdx.x;
    int loc[EE];
#pragma unroll
    for (int e = 0; e < EE; e++) loc[e] = 0;
    int start = t * EPT;
    for (int i = 0; i < EPT; i++) {
        int ev = g_topk_e[start + i];
#pragma unroll
        for (int e = 0; e < EE; e++) loc[e] += (ev == e);
    }
#pragma unroll
    for (int e = 0; e < EE; e++) sh[e][t] = loc[e];
    __syncthreads();
    if (t < EE) {
        int run = 0;
        for (int i = 0; i < ATH; i++) { int v = sh[t][i]; sh[t][i] = run; run += v; }
        g_cnt[t] = run < CAP ? run : CAP;
    }
    __syncthreads();
    int off[EE];
#pragma unroll
    for (int e = 0; e < EE; e++) off[e] = sh[e][t];
    for (int i = 0; i < EPT; i++) {
        int idx = start + i;
        int ev = g_topk_e[idx];
        int pos = 0;
#pragma unroll
        for (int e = 0; e < EE; e++) {
            if (ev == e) { pos = off[e]; off[e] = pos + 1; }
        }
        if (pos < CAP) {
            g_rows[ev * CAP + pos] = idx >> 1;
            g_slot[idx] = ev * CAP + pos;
            g_gate[idx] = g_topk_p[idx];
        } else {
            g_slot[idx] = -1;
            g_gate[idx] = 0.f;
        }
    }
}

// ---------------- HMMA grouped GEMM: fp16 2-term split, cp.async A ----------
// 128x96 tile, 256 thr, 2 CTAs/SM, K-tile 32, double-buffered, 1 barrier/tile.
// A: fp16 hi plane via cp.async.cg (no RF staging, no convert).
// B: fp32 LDG -> hi/lo fp16 split -> STS.  D = Ah*Bh + Ah*Bl.
#define AROW 80
#define BROW 208
#define APL  (128 * AROW)              // 10240 B (single A plane)
#define BPL  (32 * BROW)               // 6656 B
#define BUFB (APL + 2 * BPL)           // 23552 B per buffer
#define GEMM_SMEM (2 * BUFB)           // 47104 B per CTA

template <int MODE>
__global__ void __launch_bounds__(256, 2) moe_gemm(const float* __restrict__ W,
                                                   const float* __restrict__ bias) {
    constexpr int KDIM = (MODE == 0) ? DD : HH;
    constexpr int NDIM = (MODE == 0) ? HH : DD;
    constexpr int NT = KDIM / 32;
    extern __shared__ char smem[];

    const int e = blockIdx.z;
    const int nrows = g_cnt[e];
    const int row0 = blockIdx.y * 128;
    if (row0 >= nrows) return;
    const int col0 = blockIdx.x * 96;
    const int tid = threadIdx.x;
    const int l = tid & 31, wid = tid >> 5;
    const int wm = wid & 3, wn = wid >> 2;        // 4x2 warps: 32m x 48n each
    const uint32_t sb0 = smem_u32(smem);

    // ---- A loader: cp.async, 2 x 16B chunks per thread per K-tile ----------
    // row r = tid>>1 (0..127), chunk cc = tid&1 -> halves cc*8 and (cc+2)*8
    const int r = tid >> 1, cc = tid & 1;
    const __half* pAh;
    if (MODE == 0) {
        int tok = g_rows[e * CAP + row0 + r] & (NTOK - 1);
        pAh = g_xh + (size_t)tok * DD;
    } else {
        pAh = g_Hhi + (size_t)(e * CAP + row0 + r) * HH;
    }
    const uint32_t sAc0 = (uint32_t)(r * AROW + cc * 16);
    const uint32_t sAc1 = (uint32_t)(r * AROW + (cc + 2) * 16);
    const int aOfs0 = cc * 8, aOfs1 = (cc + 2) * 8;

    // ---- B loader (unchanged): fp32 + hi/lo split ---------------------------
    int bRow[3], bCol[3];
#pragma unroll
    for (int t = 0; t < 3; t++) {
        int c = tid + t * 256;
        bRow[t] = c / 24; bCol[t] = c % 24;
    }
    const float* Wb = W + (size_t)e * KDIM * NDIM;
    const float* pB[3];
#pragma unroll
    for (int t = 0; t < 3; t++)
        pB[t] = Wb + (size_t)bRow[t] * NDIM + col0 + bCol[t] * 4;
    uint32_t sB[3];
#pragma unroll
    for (int t = 0; t < 3; t++)
        sB[t] = (uint32_t)(bRow[t] * BROW + bCol[t] * 8);

    // ---- fragment lane offsets ----------------------------------------------
    const uint32_t offA = (uint32_t)((wm * 32 + (l & 15)) * AROW + ((l >> 4) & 1) * 16);
    const uint32_t offBt = (uint32_t)((((l & 7) + ((l >> 3) & 1) * 8)) * BROW
                                      + (l >> 4) * 16 + wn * 96);

    float acc[2][6][4];
#pragma unroll
    for (int mi = 0; mi < 2; mi++)
#pragma unroll
        for (int nj = 0; nj < 6; nj++)
#pragma unroll
            for (int q = 0; q < 4; q++) acc[mi][nj][q] = 0.f;

    // ---- prologue: cp.async A tile 0; prefetch B tile 0 regs ----------------
    CPA16(sb0 + sAc0, pAh + aOfs0);
    CPA16(sb0 + sAc1, pAh + aOfs1);
    CP_COMMIT();
    float4 bS[3];
#pragma unroll
    for (int t = 0; t < 3; t++) bS[t] = *(const float4*)pB[t];

    for (int kt = 0; kt < NT; kt++) {
        char* buf = smem + (kt & 1) * BUFB;
        const uint32_t bufu = sb0 + (kt & 1) * BUFB;
        // ---- split + store B tile kt ---------------------------------------
        {
            uint32_t h0, v0, h1, v1;
#pragma unroll
            for (int t = 0; t < 3; t++) {
                split2h(bS[t].x, bS[t].y, h0, v0); split2h(bS[t].z, bS[t].w, h1, v1);
                *(uint2*)(buf + APL + sB[t])       = make_uint2(h0, h1);
                *(uint2*)(buf + APL + BPL + sB[t]) = make_uint2(v0, v1);
            }
        }
        // ---- prefetch B tile kt+1 into regs --------------------------------
        if (kt + 1 < NT) {
            size_t kb = (size_t)(kt + 1) * 32 * NDIM;
#pragma unroll
            for (int t = 0; t < 3; t++) bS[t] = *(const float4*)(pB[t] + kb);
        }
        // ---- A tile kt must be complete; then barrier ----------------------
        CP_WAIT0();
        __syncthreads();
        // ---- issue cp.async A tile kt+1 into the other buffer --------------
        // (safe: all warps passed the barrier, so buf^1's compute is done)
        if (kt + 1 < NT) {
            const uint32_t nb = sb0 + ((kt + 1) & 1) * BUFB;
            int ka = (kt + 1) * 32;
            CPA16(nb + sAc0, pAh + ka + aOfs0);
            CPA16(nb + sAc1, pAh + ka + aOfs1);
            CP_COMMIT();
        }
        // ---- compute on buffer kt ------------------------------------------
        const uint32_t sbA = bufu;
        const uint32_t sbB = bufu + APL;
#pragma unroll
        for (int k16 = 0; k16 < 2; k16++) {
            const uint32_t kbA = k16 * 32;
            const uint32_t kbB = k16 * 16 * BROW;
            uint32_t ah0, ah1, ah2, ah3, ag0, ag1, ag2, ag3;
            ldsm4(ah0, ah1, ah2, ah3, sbA + offA + kbA);
            ldsm4(ag0, ag1, ag2, ag3, sbA + offA + 16 * AROW + kbA);
#pragma unroll
            for (int j = 0; j < 3; j++) {
                uint32_t bh0, bh1, bh2, bh3, bl0, bl1, bl2, bl3;
                ldsm4t(bh0, bh1, bh2, bh3, sbB + offBt + kbB + j * 32);
                ldsm4t(bl0, bl1, bl2, bl3, sbB + BPL + offBt + kbB + j * 32);
                mma16816(acc[0][2*j][0], acc[0][2*j][1], acc[0][2*j][2], acc[0][2*j][3],
                         ah0, ah1, ah2, ah3, bh0, bh1);
                mma16816(acc[0][2*j+1][0], acc[0][2*j+1][1], acc[0][2*j+1][2], acc[0][2*j+1][3],
                         ah0, ah1, ah2, ah3, bh2, bh3);
                mma16816(acc[1][2*j][0], acc[1][2*j][1], acc[1][2*j][2], acc[1][2*j][3],
                         ag0, ag1, ag2, ag3, bh0, bh1);
                mma16816(acc[1][2*j+1][0], acc[1][2*j+1][1], acc[1][2*j+1][2], acc[1][2*j+1][3],
                         ag0, ag1, ag2, ag3, bh2, bh3);
                mma16816(acc[0][2*j][0], acc[0][2*j][1], acc[0][2*j][2], acc[0][2*j][3],
                         ah0, ah1, ah2, ah3, bl0, bl1);
                mma16816(acc[0][2*j+1][0], acc[0][2*j+1][1], acc[0][2*j+1][2], acc[0][2*j+1][3],
                         ah0, ah1, ah2, ah3, bl2, bl3);
                mma16816(acc[1][2*j][0], acc[1][2*j][1], acc[1][2*j][2], acc[1][2*j][3],
                         ag0, ag1, ag2, ag3, bl0, bl1);
                mma16816(acc[1][2*j+1][0], acc[1][2*j+1][1], acc[1][2*j+1][2], acc[1][2*j+1][3],
                         ag0, ag1, ag2, ag3, bl2, bl3);
            }
        }
    }

    // ---- epilogue -----------------------------------------------------------
    const float s2 = 0.70710678118654752f;
    const float* bb = bias + (size_t)e * NDIM;
#pragma unroll
    for (int mi = 0; mi < 2; mi++) {
#pragma unroll
        for (int h = 0; h < 2; h++) {
            int row = row0 + wm * 32 + mi * 16 + (l >> 2) + h * 8;
            if (row >= nrows) continue;
#pragma unroll
            for (int nj = 0; nj < 6; nj++) {
                int coln = col0 + wn * 48 + nj * 8 + (l & 3) * 2;
                float v0 = acc[mi][nj][h * 2 + 0] + bb[coln];
                float v1 = acc[mi][nj][h * 2 + 1] + bb[coln + 1];
                if (MODE == 0) {
                    v0 = 0.5f * v0 * (1.0f + erff(v0 * s2));
                    v1 = 0.5f * v1 * (1.0f + erff(v1 * s2));
                    size_t idx = (size_t)(e * CAP + row) * HH + coln;
                    *reinterpret_cast<uint32_t*>(&g_Hhi[idx]) = cvt2h(v0, v1);
                } else {
                    size_t idx = (size_t)(e * CAP + row) * DD + coln;
                    float2 o2 = {v0, v1};
                    *reinterpret_cast<float2*>(&g_Ybuf[idx]) = o2;
                }
            }
        }
    }
}

// ---------------- combine ----------------------------------------------------
__global__ void combine_kernel(float* __restrict__ out) {
    int t = blockIdx.x;
    int d = threadIdx.x * 4;
    int l0 = g_slot[2 * t], l1 = g_slot[2 * t + 1];
    float g0 = g_gate[2 * t], g1 = g_gate[2 * t + 1];
    float4 r = {0.f, 0.f, 0.f, 0.f};
    if (l0 >= 0) {
        float4 y = *(const float4*)(g_Ybuf + (size_t)l0 * DD + d);
        r.x += g0 * y.x; r.y += g0 * y.y; r.z += g0 * y.z; r.w += g0 * y.w;
    }
    if (l1 >= 0) {
        float4 y = *(const float4*)(g_Ybuf + (size_t)l1 * DD + d);
        r.x += g1 * y.x; r.y += g1 * y.y; r.z += g1 * y.z; r.w += g1 * y.w;
    }
    *(float4*)(out + (size_t)t * DD + d) = r;
}

// ---------------- launch -----------------------------------------------------
extern "C" void kernel_launch(void* const* d_in, const int* in_sizes, int n_in,
                              void* d_out, int out_size) {
    (void)in_sizes; (void)n_in; (void)out_size;
    const float* x  = (const float*)d_in[0];
    const float* Wr = (const float*)d_in[1];
    const float* w1 = (const float*)d_in[2];
    const float* b1 = (const float*)d_in[3];
    const float* w2 = (const float*)d_in[4];
    const float* b2 = (const float*)d_in[5];
    float* out = (float*)d_out;

    cudaFuncSetAttribute(moe_gemm<0>, cudaFuncAttributeMaxDynamicSharedMemorySize, GEMM_SMEM);
    cudaFuncSetAttribute(moe_gemm<1>, cudaFuncAttributeMaxDynamicSharedMemorySize, GEMM_SMEM);

    cvt_x_kernel<<<(NTOK * DD / 4) / 256, 256>>>(x);
    router_kernel<<<NTOK / 8, 256>>>(x, Wr);
    assign_kernel<<<1, ATH>>>();
    moe_gemm<0><<<dim3(HH / 96, CAP / 128, EE), 256, GEMM_SMEM>>>(w1, b1);
    moe_gemm<1><<<dim3(DD / 96, CAP / 128, EE), 256, GEMM_SMEM>>>(w2, b2);
    combine_kernel<<<NTOK, DD / 4>>>(out);
}

// round 16
// speedup vs baseline: 1.0381x; 1.0381x over previous
#include <cuda_runtime.h>
#include <cuda_fp16.h>
#include <math.h>
#include <stdint.h>

// Problem constants
#define BZ 4
#define SZ 2048
#define DD 768
#define HH 3072
#define EE 8
#define NTOK (BZ*SZ)          // 8192
#define NENT (NTOK*2)         // 16384
#define CAP  1536
#define ROWS_MAX (EE*CAP)     // 12288

// ---------------- device scratch (170 MB, under proven 189 MB bound) --------
__device__ int   g_topk_e[NENT];
__device__ float g_topk_p[NENT];
__device__ int   g_rows[ROWS_MAX];
__device__ int   g_cnt[EE];
__device__ int   g_slot[NENT];
__device__ float g_gate[NENT];
__device__ __half g_Hhi[(size_t)ROWS_MAX * HH];        // 75.5 MB fp16 H
__device__ __half g_Yh [(size_t)ROWS_MAX * DD];        // 18.9 MB fp16 Y
__device__ __half g_w2s[(size_t)EE * HH * 2 * DD];     // 75.5 MB w2 hi/lo planes

// ---------------- PTX helpers -----------------------------------------------
__device__ __forceinline__ uint32_t smem_u32(const void* p) {
    uint32_t a;
    asm("{ .reg .u64 t; cvta.to.shared.u64 t, %1; cvt.u32.u64 %0, t; }" : "=r"(a) : "l"(p));
    return a;
}
__device__ __forceinline__ void ldsm4(uint32_t& r0, uint32_t& r1, uint32_t& r2, uint32_t& r3,
                                      uint32_t addr) {
    asm volatile("ldmatrix.sync.aligned.m8n8.x4.shared.b16 {%0,%1,%2,%3}, [%4];"
                 : "=r"(r0), "=r"(r1), "=r"(r2), "=r"(r3) : "r"(addr));
}
__device__ __forceinline__ void ldsm4t(uint32_t& r0, uint32_t& r1, uint32_t& r2, uint32_t& r3,
                                       uint32_t addr) {
    asm volatile("ldmatrix.sync.aligned.m8n8.x4.trans.shared.b16 {%0,%1,%2,%3}, [%4];"
                 : "=r"(r0), "=r"(r1), "=r"(r2), "=r"(r3) : "r"(addr));
}
__device__ __forceinline__ void mma16816(float& c0, float& c1, float& c2, float& c3,
                                         uint32_t a0, uint32_t a1, uint32_t a2, uint32_t a3,
                                         uint32_t b0, uint32_t b1) {
    asm volatile("mma.sync.aligned.m16n8k16.row.col.f32.f16.f16.f32 "
                 "{%0,%1,%2,%3}, {%4,%5,%6,%7}, {%8,%9}, {%0,%1,%2,%3};"
                 : "+f"(c0), "+f"(c1), "+f"(c2), "+f"(c3)
                 : "r"(a0), "r"(a1), "r"(a2), "r"(a3), "r"(b0), "r"(b1));
}
__device__ __forceinline__ uint32_t cvt2h(float f0, float f1) {
    __half2 h = __floats2half2_rn(f0, f1);
    return *reinterpret_cast<uint32_t*>(&h);
}
__device__ __forceinline__ void split2h(float f0, float f1, uint32_t& hi, uint32_t& lo) {
    __half h0 = __float2half_rn(f0), h1 = __float2half_rn(f1);
    __half l0 = __float2half_rn(f0 - __half2float(h0));
    __half l1 = __float2half_rn(f1 - __half2float(h1));
    hi = (uint32_t)*(unsigned short*)&h0 | ((uint32_t)*(unsigned short*)&h1 << 16);
    lo = (uint32_t)*(unsigned short*)&l0 | ((uint32_t)*(unsigned short*)&l1 << 16);
}

// ---------------- pre-pass: split w2 into interleaved hi/lo fp16 rows -------
// w2: [e][k][D] fp32 -> g_w2s: [e][k][2][D] fp16 (hi row, then lo row)
__global__ void split_w2_kernel(const float* __restrict__ w2) {
    int i = blockIdx.x * blockDim.x + threadIdx.x;   // float4 index
    int rowk = i / (DD / 4);                          // global e*HH + k
    int c4   = i % (DD / 4);
    float4 v = reinterpret_cast<const float4*>(w2)[i];
    uint32_t h0, l0, h1, l1;
    split2h(v.x, v.y, h0, l0);
    split2h(v.z, v.w, h1, l1);
    size_t hi = ((size_t)rowk * 2) * DD + c4 * 4;
    *reinterpret_cast<uint2*>(&g_w2s[hi])      = make_uint2(h0, h1);
    *reinterpret_cast<uint2*>(&g_w2s[hi + DD]) = make_uint2(l0, l1);
}

// ---------------- router -----------------------------------------------------
__global__ void router_kernel(const float* __restrict__ x,
                              const float* __restrict__ Wr) {
    int warp = threadIdx.x >> 5;
    int lane = threadIdx.x & 31;
    int t = blockIdx.x * 8 + warp;
    if (t >= NTOK) return;
    const float* xr = x + (size_t)t * DD;
    float acc[EE];
#pragma unroll
    for (int e = 0; e < EE; e++) acc[e] = 0.f;
    for (int i = lane; i < DD; i += 32) {
        float xv = xr[i];
        const float4* wr4 = reinterpret_cast<const float4*>(Wr + i * EE);
        float4 w0 = wr4[0], w1 = wr4[1];
        acc[0] += xv * w0.x; acc[1] += xv * w0.y;
        acc[2] += xv * w0.z; acc[3] += xv * w0.w;
        acc[4] += xv * w1.x; acc[5] += xv * w1.y;
        acc[6] += xv * w1.z; acc[7] += xv * w1.w;
    }
#pragma unroll
    for (int e = 0; e < EE; e++)
#pragma unroll
        for (int o = 16; o > 0; o >>= 1)
            acc[e] += __shfl_xor_sync(0xffffffffu, acc[e], o);
    if (lane == 0) {
        float m = acc[0];
#pragma unroll
        for (int e = 1; e < EE; e++) m = fmaxf(m, acc[e]);
        float p[EE]; float s = 0.f;
#pragma unroll
        for (int e = 0; e < EE; e++) { p[e] = expf(acc[e] - m); s += p[e]; }
        float inv = 1.f / s;
#pragma unroll
        for (int e = 0; e < EE; e++) p[e] *= inv;
        int i0 = 0;
#pragma unroll
        for (int e = 1; e < EE; e++) if (p[e] > p[i0]) i0 = e;
        int i1 = -1;
#pragma unroll
        for (int e = 0; e < EE; e++) {
            if (e == i0) continue;
            if (i1 < 0 || p[e] > p[i1]) i1 = e;
        }
        float ps = 1.f / (p[i0] + p[i1]);
        g_topk_e[2 * t + 0] = i0; g_topk_p[2 * t + 0] = p[i0] * ps;
        g_topk_e[2 * t + 1] = i1; g_topk_p[2 * t + 1] = p[i1] * ps;
    }
}

// ---------------- capacity assignment (exact flat-order) ---------------------
#define ATH 512
#define EPT (NENT / ATH)
__global__ void assign_kernel() {
    __shared__ int sh[EE][ATH];
    int t = threadIdx.x;
    int loc[EE];
#pragma unroll
    for (int e = 0; e < EE; e++) loc[e] = 0;
    int start = t * EPT;
    for (int i = 0; i < EPT; i++) {
        int ev = g_topk_e[start + i];
#pragma unroll
        for (int e = 0; e < EE; e++) loc[e] += (ev == e);
    }
#pragma unroll
    for (int e = 0; e < EE; e++) sh[e][t] = loc[e];
    __syncthreads();
    if (t < EE) {
        int run = 0;
        for (int i = 0; i < ATH; i++) { int v = sh[t][i]; sh[t][i] = run; run += v; }
        g_cnt[t] = run < CAP ? run : CAP;
    }
    __syncthreads();
    int off[EE];
#pragma unroll
    for (int e = 0; e < EE; e++) off[e] = sh[e][t];
    for (int i = 0; i < EPT; i++) {
        int idx = start + i;
        int ev = g_topk_e[idx];
        int pos = 0;
#pragma unroll
        for (int e = 0; e < EE; e++) {
            if (ev == e) { pos = off[e]; off[e] = pos + 1; }
        }
        if (pos < CAP) {
            g_rows[ev * CAP + pos] = idx >> 1;
            g_slot[idx] = ev * CAP + pos;
            g_gate[idx] = g_topk_p[idx];
        } else {
            g_slot[idx] = -1;
            g_gate[idx] = 0.f;
        }
    }
}

// ---------------- HMMA grouped GEMM: fp16 2-term split -----------------------
// R14-identical pipeline (register-staged, 1 barrier/K-tile, 2 CTAs/SM).
// MODE 0: A = gather(x) fp32->fp16 cvt in loader; B = w1 fp32 ->split in loader.
// MODE 1: A = g_Hhi fp16 direct; B = g_w2s fp16 hi/lo direct (no conversion).
#define AROW 80
#define BROW 208
#define APL  (128 * AROW)              // 10240 B (single A plane)
#define BPL  (32 * BROW)               // 6656 B
#define BUFB (APL + 2 * BPL)           // 23552 B per buffer
#define GEMM_SMEM (2 * BUFB)           // 47104 B per CTA

template <int MODE>
__global__ void __launch_bounds__(256, 2) moe_gemm(const float* __restrict__ X,
                                                   const float* __restrict__ W,
                                                   const float* __restrict__ bias) {
    constexpr int KDIM = (MODE == 0) ? DD : HH;
    constexpr int NDIM = (MODE == 0) ? HH : DD;
    constexpr int NT = KDIM / 32;
    extern __shared__ char smem[];

    const int e = blockIdx.z;
    const int nrows = g_cnt[e];
    const int row0 = blockIdx.y * 128;
    if (row0 >= nrows) return;
    const int col0 = blockIdx.x * 96;
    const int tid = threadIdx.x;
    const int l = tid & 31, wid = tid >> 5;
    const int wm = wid & 3, wn = wid >> 2;        // 4x2 warps: 32m x 48n each
    const uint32_t sb0 = smem_u32(smem);

    // ---- A loader -----------------------------------------------------------
    const int am = tid >> 3, akc = tid & 7;       // MODE 0: 4 float4 chunks
    const int rh = tid >> 2, kh = tid & 3;        // MODE 1: 2 uint4 chunks
    const float*  pA[4];
    const __half* pAh[2];
#pragma unroll
    for (int g = 0; g < 4; g++) pA[g] = nullptr;
    pAh[0] = pAh[1] = nullptr;
    if (MODE == 0) {
#pragma unroll
        for (int g = 0; g < 4; g++) {
            int tok = g_rows[e * CAP + row0 + am + 32 * g] & (NTOK - 1);
            pA[g] = X + (size_t)tok * DD + akc * 4;
        }
    } else {
#pragma unroll
        for (int t = 0; t < 2; t++)
            pAh[t] = g_Hhi + (size_t)(e * CAP + row0 + rh + 64 * t) * HH + kh * 8;
    }
    const uint32_t sA  = (uint32_t)(am * AROW + akc * 8);
    const uint32_t sAh = (uint32_t)(rh * AROW + kh * 16);

    // ---- B loader -----------------------------------------------------------
    // MODE 0: fp32 w1, 3 float4 chunks/thread, split in loader (R14-identical).
    // MODE 1: fp16 w2s, 3 uint4 chunks/thread (hi/lo rows), direct STS.
    int bRow[3], bCol[3];
    const float*  pB[3];
    const __half* pBh[3];
    uint32_t sB[3], sBq[3];
    if (MODE == 0) {
#pragma unroll
        for (int t = 0; t < 3; t++) {
            int c = tid + t * 256;
            bRow[t] = c / 24; bCol[t] = c % 24;
            pB[t] = W + (size_t)e * KDIM * NDIM + (size_t)bRow[t] * NDIM + col0 + bCol[t] * 4;
            sB[t] = (uint32_t)(bRow[t] * BROW + bCol[t] * 8);
            pBh[t] = nullptr; sBq[t] = 0;
        }
    } else {
#pragma unroll
        for (int t = 0; t < 3; t++) {
            int c = tid + t * 256;            // 768 chunks: 32 k x 2 planes x 12
            int r = c / 24, rem = c % 24;
            int p = rem / 12, j = rem % 12;
            pBh[t] = g_w2s + ((size_t)(e * HH + r) * 2 + p) * DD + col0 + j * 8;
            sBq[t] = (uint32_t)(p * BPL + r * BROW + j * 16);
            pB[t] = nullptr; sB[t] = 0;
        }
    }

    // ---- fragment lane offsets ----------------------------------------------
    const uint32_t offA = (uint32_t)((wm * 32 + (l & 15)) * AROW + ((l >> 4) & 1) * 16);
    const uint32_t offBt = (uint32_t)((((l & 7) + ((l >> 3) & 1) * 8)) * BROW
                                      + (l >> 4) * 16 + wn * 96);

    float acc[2][6][4];
#pragma unroll
    for (int mi = 0; mi < 2; mi++)
#pragma unroll
        for (int nj = 0; nj < 6; nj++)
#pragma unroll
            for (int q = 0; q < 4; q++) acc[mi][nj][q] = 0.f;

    // ---- prefetch tile 0 ----------------------------------------------------
    float4 aS[4], bS[3];
    uint4  aH[2], bH[3];
    if (MODE == 0) {
#pragma unroll
        for (int g = 0; g < 4; g++) aS[g] = *(const float4*)pA[g];
#pragma unroll
        for (int t = 0; t < 3; t++) bS[t] = *(const float4*)pB[t];
    } else {
#pragma unroll
        for (int t = 0; t < 2; t++) aH[t] = *(const uint4*)pAh[t];
#pragma unroll
        for (int t = 0; t < 3; t++) bH[t] = *(const uint4*)pBh[t];
    }

    for (int kt = 0; kt < NT; kt++) {
        char* buf = smem + (kt & 1) * BUFB;
        // ---- store current tile ---------------------------------------------
        if (MODE == 0) {
#pragma unroll
            for (int g = 0; g < 4; g++) {
                uint32_t h0 = cvt2h(aS[g].x, aS[g].y);
                uint32_t h1 = cvt2h(aS[g].z, aS[g].w);
                *(uint2*)(buf + sA + g * 32 * AROW) = make_uint2(h0, h1);
            }
            uint32_t h0, v0, h1, v1;
#pragma unroll
            for (int t = 0; t < 3; t++) {
                split2h(bS[t].x, bS[t].y, h0, v0); split2h(bS[t].z, bS[t].w, h1, v1);
                *(uint2*)(buf + APL + sB[t])       = make_uint2(h0, h1);
                *(uint2*)(buf + APL + BPL + sB[t]) = make_uint2(v0, v1);
            }
        } else {
#pragma unroll
            for (int t = 0; t < 2; t++)
                *(uint4*)(buf + sAh + t * 64 * AROW) = aH[t];
#pragma unroll
            for (int t = 0; t < 3; t++)
                *(uint4*)(buf + APL + sBq[t]) = bH[t];
        }
        // ---- prefetch next tile ---------------------------------------------
        if (kt + 1 < NT) {
            size_t ka = (size_t)(kt + 1) * 32;
            if (MODE == 0) {
                size_t kb = (size_t)(kt + 1) * 32 * NDIM;
#pragma unroll
                for (int g = 0; g < 4; g++) aS[g] = *(const float4*)(pA[g] + ka);
#pragma unroll
                for (int t = 0; t < 3; t++) bS[t] = *(const float4*)(pB[t] + kb);
            } else {
                size_t kb = (size_t)(kt + 1) * 64 * DD;   // 32 k-rows x 2 planes
#pragma unroll
                for (int t = 0; t < 2; t++) aH[t] = *(const uint4*)(pAh[t] + ka);
#pragma unroll
                for (int t = 0; t < 3; t++) bH[t] = *(const uint4*)(pBh[t] + kb);
            }
        }
        __syncthreads();
        // ---- compute on this buffer -----------------------------------------
        const uint32_t sbA = sb0 + (kt & 1) * BUFB;
        const uint32_t sbB = sbA + APL;
#pragma unroll
        for (int k16 = 0; k16 < 2; k16++) {
            const uint32_t kbA = k16 * 32;
            const uint32_t kbB = k16 * 16 * BROW;
            uint32_t ah0, ah1, ah2, ah3, ag0, ag1, ag2, ag3;
            ldsm4(ah0, ah1, ah2, ah3, sbA + offA + kbA);
            ldsm4(ag0, ag1, ag2, ag3, sbA + offA + 16 * AROW + kbA);
#pragma unroll
            for (int j = 0; j < 3; j++) {
                uint32_t bh0, bh1, bh2, bh3, bl0, bl1, bl2, bl3;
                ldsm4t(bh0, bh1, bh2, bh3, sbB + offBt + kbB + j * 32);
                ldsm4t(bl0, bl1, bl2, bl3, sbB + BPL + offBt + kbB + j * 32);
                mma16816(acc[0][2*j][0], acc[0][2*j][1], acc[0][2*j][2], acc[0][2*j][3],
                         ah0, ah1, ah2, ah3, bh0, bh1);
                mma16816(acc[0][2*j+1][0], acc[0][2*j+1][1], acc[0][2*j+1][2], acc[0][2*j+1][3],
                         ah0, ah1, ah2, ah3, bh2, bh3);
                mma16816(acc[1][2*j][0], acc[1][2*j][1], acc[1][2*j][2], acc[1][2*j][3],
                         ag0, ag1, ag2, ag3, bh0, bh1);
                mma16816(acc[1][2*j+1][0], acc[1][2*j+1][1], acc[1][2*j+1][2], acc[1][2*j+1][3],
                         ag0, ag1, ag2, ag3, bh2, bh3);
                mma16816(acc[0][2*j][0], acc[0][2*j][1], acc[0][2*j][2], acc[0][2*j][3],
                         ah0, ah1, ah2, ah3, bl0, bl1);
                mma16816(acc[0][2*j+1][0], acc[0][2*j+1][1], acc[0][2*j+1][2], acc[0][2*j+1][3],
                         ah0, ah1, ah2, ah3, bl2, bl3);
                mma16816(acc[1][2*j][0], acc[1][2*j][1], acc[1][2*j][2], acc[1][2*j][3],
                         ag0, ag1, ag2, ag3, bl0, bl1);
                mma16816(acc[1][2*j+1][0], acc[1][2*j+1][1], acc[1][2*j+1][2], acc[1][2*j+1][3],
                         ag0, ag1, ag2, ag3, bl2, bl3);
            }
        }
    }

    // ---- epilogue -----------------------------------------------------------
    const float s2 = 0.70710678118654752f;
    const float* bb = bias + (size_t)e * NDIM;
#pragma unroll
    for (int mi = 0; mi < 2; mi++) {
#pragma unroll
        for (int h = 0; h < 2; h++) {
            int row = row0 + wm * 32 + mi * 16 + (l >> 2) + h * 8;
            if (row >= nrows) continue;
#pragma unroll
            for (int nj = 0; nj < 6; nj++) {
                int coln = col0 + wn * 48 + nj * 8 + (l & 3) * 2;
                float v0 = acc[mi][nj][h * 2 + 0] + bb[coln];
                float v1 = acc[mi][nj][h * 2 + 1] + bb[coln + 1];
                if (MODE == 0) {
                    v0 = 0.5f * v0 * (1.0f + erff(v0 * s2));
                    v1 = 0.5f * v1 * (1.0f + erff(v1 * s2));
                    size_t idx = (size_t)(e * CAP + row) * HH + coln;
                    *reinterpret_cast<uint32_t*>(&g_Hhi[idx]) = cvt2h(v0, v1);
                } else {
                    size_t idx = (size_t)(e * CAP + row) * DD + coln;
                    *reinterpret_cast<uint32_t*>(&g_Yh[idx]) = cvt2h(v0, v1);
                }
            }
        }
    }
}

// ---------------- combine (fp16 Y) -------------------------------------------
__global__ void combine_kernel(float* __restrict__ out) {
    int t = blockIdx.x;
    int d = threadIdx.x * 4;
    int l0 = g_slot[2 * t], l1 = g_slot[2 * t + 1];
    float g0 = g_gate[2 * t], g1 = g_gate[2 * t + 1];
    float4 r = {0.f, 0.f, 0.f, 0.f};
    if (l0 >= 0) {
        uint2 q = *(const uint2*)(g_Yh + (size_t)l0 * DD + d);
        __half2 a = *reinterpret_cast<__half2*>(&q.x);
        __half2 b = *reinterpret_cast<__half2*>(&q.y);
        r.x += g0 * __low2float(a);  r.y += g0 * __high2float(a);
        r.z += g0 * __low2float(b);  r.w += g0 * __high2float(b);
    }
    if (l1 >= 0) {
        uint2 q = *(const uint2*)(g_Yh + (size_t)l1 * DD + d);
        __half2 a = *reinterpret_cast<__half2*>(&q.x);
        __half2 b = *reinterpret_cast<__half2*>(&q.y);
        r.x += g1 * __low2float(a);  r.y += g1 * __high2float(a);
        r.z += g1 * __low2float(b);  r.w += g1 * __high2float(b);
    }
    *(float4*)(out + (size_t)t * DD + d) = r;
}

// ---------------- launch -----------------------------------------------------
extern "C" void kernel_launch(void* const* d_in, const int* in_sizes, int n_in,
                              void* d_out, int out_size) {
    (void)in_sizes; (void)n_in; (void)out_size;
    const float* x  = (const float*)d_in[0];
    const float* Wr = (const float*)d_in[1];
    const float* w1 = (const float*)d_in[2];
    const float* b1 = (const float*)d_in[3];
    const float* w2 = (const float*)d_in[4];
    const float* b2 = (const float*)d_in[5];
    float* out = (float*)d_out;

    cudaFuncSetAttribute(moe_gemm<0>, cudaFuncAttributeMaxDynamicSharedMemorySize, GEMM_SMEM);
    cudaFuncSetAttribute(moe_gemm<1>, cudaFuncAttributeMaxDynamicSharedMemorySize, GEMM_SMEM);

    split_w2_kernel<<<(EE * HH * DD / 4) / 256, 256>>>(w2);
    router_kernel<<<NTOK / 8, 256>>>(x, Wr);
    assign_kernel<<<1, ATH>>>();
    moe_gemm<0><<<dim3(HH / 96, CAP / 128, EE), 256, GEMM_SMEM>>>(x, w1, b1);
    moe_gemm<1><<<dim3(DD / 96, CAP / 128, EE), 256, GEMM_SMEM>>>(nullptr, nullptr, b2);
    combine_kernel<<<NTOK, DD / 4>>>(out);
}

// round 17
// speedup vs baseline: 1.0838x; 1.0440x over previous
#include <cuda_runtime.h>
#include <cuda_fp16.h>
#include <math.h>
#include <stdint.h>

// Problem constants
#define BZ 4
#define SZ 2048
#define DD 768
#define HH 3072
#define EE 8
#define NTOK (BZ*SZ)          // 8192
#define NENT (NTOK*2)         // 16384
#define CAP  1536
#define ROWS_MAX (EE*CAP)     // 12288

// ---------------- device scratch (88.6 MB, far under proven 189 MB bound) ---
__device__ int   g_topk_e[NENT];
__device__ float g_topk_p[NENT];
__device__ int   g_rows[ROWS_MAX];
__device__ float g_gslot[ROWS_MAX];               // gate per kept slot
__device__ int   g_cnt[EE];
__device__ __half g_xh [(size_t)NTOK * DD];       // 12.6 MB fp16 x
__device__ __half g_Hhi[(size_t)ROWS_MAX * HH];   // 75.5 MB fp16 H

// ---------------- PTX helpers -----------------------------------------------
__device__ __forceinline__ uint32_t smem_u32(const void* p) {
    uint32_t a;
    asm("{ .reg .u64 t; cvta.to.shared.u64 t, %1; cvt.u32.u64 %0, t; }" : "=r"(a) : "l"(p));
    return a;
}
__device__ __forceinline__ void ldsm4(uint32_t& r0, uint32_t& r1, uint32_t& r2, uint32_t& r3,
                                      uint32_t addr) {
    asm volatile("ldmatrix.sync.aligned.m8n8.x4.shared.b16 {%0,%1,%2,%3}, [%4];"
                 : "=r"(r0), "=r"(r1), "=r"(r2), "=r"(r3) : "r"(addr));
}
__device__ __forceinline__ void ldsm4t(uint32_t& r0, uint32_t& r1, uint32_t& r2, uint32_t& r3,
                                       uint32_t addr) {
    asm volatile("ldmatrix.sync.aligned.m8n8.x4.trans.shared.b16 {%0,%1,%2,%3}, [%4];"
                 : "=r"(r0), "=r"(r1), "=r"(r2), "=r"(r3) : "r"(addr));
}
__device__ __forceinline__ void mma16816(float& c0, float& c1, float& c2, float& c3,
                                         uint32_t a0, uint32_t a1, uint32_t a2, uint32_t a3,
                                         uint32_t b0, uint32_t b1) {
    asm volatile("mma.sync.aligned.m16n8k16.row.col.f32.f16.f16.f32 "
                 "{%0,%1,%2,%3}, {%4,%5,%6,%7}, {%8,%9}, {%0,%1,%2,%3};"
                 : "+f"(c0), "+f"(c1), "+f"(c2), "+f"(c3)
                 : "r"(a0), "r"(a1), "r"(a2), "r"(a3), "r"(b0), "r"(b1));
}
__device__ __forceinline__ uint32_t cvt2h(float f0, float f1) {
    __half2 h = __floats2half2_rn(f0, f1);
    return *reinterpret_cast<uint32_t*>(&h);
}
__device__ __forceinline__ void split2h(float f0, float f1, uint32_t& hi, uint32_t& lo) {
    __half h0 = __float2half_rn(f0), h1 = __float2half_rn(f1);
    __half l0 = __float2half_rn(f0 - __half2float(h0));
    __half l1 = __float2half_rn(f1 - __half2float(h1));
    hi = (uint32_t)*(unsigned short*)&h0 | ((uint32_t)*(unsigned short*)&h1 << 16);
    lo = (uint32_t)*(unsigned short*)&l0 | ((uint32_t)*(unsigned short*)&l1 << 16);
}

// ---------------- pre-pass: x -> fp16; zero output ---------------------------
__global__ void cvt_x_kernel(const float* __restrict__ x) {
    int i = blockIdx.x * blockDim.x + threadIdx.x;
    float4 v = reinterpret_cast<const float4*>(x)[i];
    uint2 q;
    q.x = cvt2h(v.x, v.y);
    q.y = cvt2h(v.z, v.w);
    *reinterpret_cast<uint2*>(&g_xh[i * 4]) = q;
}
__global__ void zero_out_kernel(float* __restrict__ out) {
    int i = blockIdx.x * blockDim.x + threadIdx.x;
    float4 z = {0.f, 0.f, 0.f, 0.f};
    reinterpret_cast<float4*>(out)[i] = z;
}

// ---------------- router -----------------------------------------------------
__global__ void router_kernel(const float* __restrict__ x,
                              const float* __restrict__ Wr) {
    int warp = threadIdx.x >> 5;
    int lane = threadIdx.x & 31;
    int t = blockIdx.x * 8 + warp;
    if (t >= NTOK) return;
    const float* xr = x + (size_t)t * DD;
    float acc[EE];
#pragma unroll
    for (int e = 0; e < EE; e++) acc[e] = 0.f;
    for (int i = lane; i < DD; i += 32) {
        float xv = xr[i];
        const float4* wr4 = reinterpret_cast<const float4*>(Wr + i * EE);
        float4 w0 = wr4[0], w1 = wr4[1];
        acc[0] += xv * w0.x; acc[1] += xv * w0.y;
        acc[2] += xv * w0.z; acc[3] += xv * w0.w;
        acc[4] += xv * w1.x; acc[5] += xv * w1.y;
        acc[6] += xv * w1.z; acc[7] += xv * w1.w;
    }
#pragma unroll
    for (int e = 0; e < EE; e++)
#pragma unroll
        for (int o = 16; o > 0; o >>= 1)
            acc[e] += __shfl_xor_sync(0xffffffffu, acc[e], o);
    if (lane == 0) {
        float m = acc[0];
#pragma unroll
        for (int e = 1; e < EE; e++) m = fmaxf(m, acc[e]);
        float p[EE]; float s = 0.f;
#pragma unroll
        for (int e = 0; e < EE; e++) { p[e] = expf(acc[e] - m); s += p[e]; }
        float inv = 1.f / s;
#pragma unroll
        for (int e = 0; e < EE; e++) p[e] *= inv;
        int i0 = 0;
#pragma unroll
        for (int e = 1; e < EE; e++) if (p[e] > p[i0]) i0 = e;
        int i1 = -1;
#pragma unroll
        for (int e = 0; e < EE; e++) {
            if (e == i0) continue;
            if (i1 < 0 || p[e] > p[i1]) i1 = e;
        }
        float ps = 1.f / (p[i0] + p[i1]);
        g_topk_e[2 * t + 0] = i0; g_topk_p[2 * t + 0] = p[i0] * ps;
        g_topk_e[2 * t + 1] = i1; g_topk_p[2 * t + 1] = p[i1] * ps;
    }
}

// ---------------- capacity assignment (exact flat-order) ---------------------
#define ATH 512
#define EPT (NENT / ATH)
__global__ void assign_kernel() {
    __shared__ int sh[EE][ATH];
    int t = threadIdx.x;
    int loc[EE];
#pragma unroll
    for (int e = 0; e < EE; e++) loc[e] = 0;
    int start = t * EPT;
    for (int i = 0; i < EPT; i++) {
        int ev = g_topk_e[start + i];
#pragma unroll
        for (int e = 0; e < EE; e++) loc[e] += (ev == e);
    }
#pragma unroll
    for (int e = 0; e < EE; e++) sh[e][t] = loc[e];
    __syncthreads();
    if (t < EE) {
        int run = 0;
        for (int i = 0; i < ATH; i++) { int v = sh[t][i]; sh[t][i] = run; run += v; }
        g_cnt[t] = run < CAP ? run : CAP;
    }
    __syncthreads();
    int off[EE];
#pragma unroll
    for (int e = 0; e < EE; e++) off[e] = sh[e][t];
    for (int i = 0; i < EPT; i++) {
        int idx = start + i;
        int ev = g_topk_e[idx];
        int pos = 0;
#pragma unroll
        for (int e = 0; e < EE; e++) {
            if (ev == e) { pos = off[e]; off[e] = pos + 1; }
        }
        if (pos < CAP) {
            g_rows [ev * CAP + pos] = idx >> 1;
            g_gslot[ev * CAP + pos] = g_topk_p[idx];
        }
    }
}

// ---------------- HMMA grouped GEMM: fp16 2-term split -----------------------
// 128x96 tile, 256 thr, 2 CTAs/SM, K-tile 32, double-buffered, 1 barrier/tile.
// A: fp16 direct (g_xh gather for MODE 0, g_Hhi for MODE 1).
// B: fp32 LDG -> hi/lo fp16 split in loader. D = Ah*Bh + Ah*Bl.
// MODE 0 epilogue -> g_Hhi fp16; MODE 1 epilogue -> atomicAdd gate*v into out.
#define AROW 80
#define BROW 208
#define APL  (128 * AROW)              // 10240 B (single A plane)
#define BPL  (32 * BROW)               // 6656 B
#define BUFB (APL + 2 * BPL)           // 23552 B per buffer
#define GEMM_SMEM (2 * BUFB)           // 47104 B per CTA

template <int MODE>
__global__ void __launch_bounds__(256, 2) moe_gemm(const float* __restrict__ W,
                                                   const float* __restrict__ bias,
                                                   float* __restrict__ out) {
    constexpr int KDIM = (MODE == 0) ? DD : HH;
    constexpr int NDIM = (MODE == 0) ? HH : DD;
    constexpr int NT = KDIM / 32;
    extern __shared__ char smem[];

    const int e = blockIdx.z;
    const int nrows = g_cnt[e];
    const int row0 = blockIdx.y * 128;
    if (row0 >= nrows) return;
    const int col0 = blockIdx.x * 96;
    const int tid = threadIdx.x;
    const int l = tid & 31, wid = tid >> 5;
    const int wm = wid & 3, wn = wid >> 2;        // 4x2 warps: 32m x 48n each
    const uint32_t sb0 = smem_u32(smem);

    // ---- A loader: fp16 direct, 2 x uint4 chunks/thread/K-tile -------------
    const int rh = tid >> 2, kh = tid & 3;
    const __half* pAh[2];
    if (MODE == 0) {
        int t0 = g_rows[e * CAP + row0 + rh]      & (NTOK - 1);
        int t1 = g_rows[e * CAP + row0 + rh + 64] & (NTOK - 1);
        pAh[0] = g_xh + (size_t)t0 * DD + kh * 8;
        pAh[1] = g_xh + (size_t)t1 * DD + kh * 8;
    } else {
        pAh[0] = g_Hhi + (size_t)(e * CAP + row0 + rh) * HH + kh * 8;
        pAh[1] = g_Hhi + (size_t)(e * CAP + row0 + rh + 64) * HH + kh * 8;
    }
    const uint32_t sAh = (uint32_t)(rh * AROW + kh * 16);

    // ---- B loader: fp32 + hi/lo split (R14-identical) -----------------------
    int bRow[3], bCol[3];
#pragma unroll
    for (int t = 0; t < 3; t++) {
        int c = tid + t * 256;
        bRow[t] = c / 24; bCol[t] = c % 24;
    }
    const float* Wb = W + (size_t)e * KDIM * NDIM;
    const float* pB[3];
#pragma unroll
    for (int t = 0; t < 3; t++)
        pB[t] = Wb + (size_t)bRow[t] * NDIM + col0 + bCol[t] * 4;
    uint32_t sB[3];
#pragma unroll
    for (int t = 0; t < 3; t++)
        sB[t] = (uint32_t)(bRow[t] * BROW + bCol[t] * 8);

    // ---- fragment lane offsets ----------------------------------------------
    const uint32_t offA = (uint32_t)((wm * 32 + (l & 15)) * AROW + ((l >> 4) & 1) * 16);
    const uint32_t offBt = (uint32_t)((((l & 7) + ((l >> 3) & 1) * 8)) * BROW
                                      + (l >> 4) * 16 + wn * 96);

    float acc[2][6][4];
#pragma unroll
    for (int mi = 0; mi < 2; mi++)
#pragma unroll
        for (int nj = 0; nj < 6; nj++)
#pragma unroll
            for (int q = 0; q < 4; q++) acc[mi][nj][q] = 0.f;

    // ---- prefetch tile 0 ----------------------------------------------------
    uint4 aH[2];
    float4 bS[3];
#pragma unroll
    for (int t = 0; t < 2; t++) aH[t] = *(const uint4*)pAh[t];
#pragma unroll
    for (int t = 0; t < 3; t++) bS[t] = *(const float4*)pB[t];

    for (int kt = 0; kt < NT; kt++) {
        char* buf = smem + (kt & 1) * BUFB;
        // ---- store current tile ---------------------------------------------
#pragma unroll
        for (int t = 0; t < 2; t++)
            *(uint4*)(buf + sAh + t * 64 * AROW) = aH[t];
        {
            uint32_t h0, v0, h1, v1;
#pragma unroll
            for (int t = 0; t < 3; t++) {
                split2h(bS[t].x, bS[t].y, h0, v0); split2h(bS[t].z, bS[t].w, h1, v1);
                *(uint2*)(buf + APL + sB[t])       = make_uint2(h0, h1);
                *(uint2*)(buf + APL + BPL + sB[t]) = make_uint2(v0, v1);
            }
        }
        // ---- prefetch next tile ---------------------------------------------
        if (kt + 1 < NT) {
            size_t ka = (size_t)(kt + 1) * 32;
            size_t kb = (size_t)(kt + 1) * 32 * NDIM;
#pragma unroll
            for (int t = 0; t < 2; t++) aH[t] = *(const uint4*)(pAh[t] + ka);
#pragma unroll
            for (int t = 0; t < 3; t++) bS[t] = *(const float4*)(pB[t] + kb);
        }
        __syncthreads();
        // ---- compute on this buffer -----------------------------------------
        const uint32_t sbA = sb0 + (kt & 1) * BUFB;
        const uint32_t sbB = sbA + APL;
#pragma unroll
        for (int k16 = 0; k16 < 2; k16++) {
            const uint32_t kbA = k16 * 32;
            const uint32_t kbB = k16 * 16 * BROW;
            uint32_t ah0, ah1, ah2, ah3, ag0, ag1, ag2, ag3;
            ldsm4(ah0, ah1, ah2, ah3, sbA + offA + kbA);
            ldsm4(ag0, ag1, ag2, ag3, sbA + offA + 16 * AROW + kbA);
#pragma unroll
            for (int j = 0; j < 3; j++) {
                uint32_t bh0, bh1, bh2, bh3, bl0, bl1, bl2, bl3;
                ldsm4t(bh0, bh1, bh2, bh3, sbB + offBt + kbB + j * 32);
                ldsm4t(bl0, bl1, bl2, bl3, sbB + BPL + offBt + kbB + j * 32);
                mma16816(acc[0][2*j][0], acc[0][2*j][1], acc[0][2*j][2], acc[0][2*j][3],
                         ah0, ah1, ah2, ah3, bh0, bh1);
                mma16816(acc[0][2*j+1][0], acc[0][2*j+1][1], acc[0][2*j+1][2], acc[0][2*j+1][3],
                         ah0, ah1, ah2, ah3, bh2, bh3);
                mma16816(acc[1][2*j][0], acc[1][2*j][1], acc[1][2*j][2], acc[1][2*j][3],
                         ag0, ag1, ag2, ag3, bh0, bh1);
                mma16816(acc[1][2*j+1][0], acc[1][2*j+1][1], acc[1][2*j+1][2], acc[1][2*j+1][3],
                         ag0, ag1, ag2, ag3, bh2, bh3);
                mma16816(acc[0][2*j][0], acc[0][2*j][1], acc[0][2*j][2], acc[0][2*j][3],
                         ah0, ah1, ah2, ah3, bl0, bl1);
                mma16816(acc[0][2*j+1][0], acc[0][2*j+1][1], acc[0][2*j+1][2], acc[0][2*j+1][3],
                         ah0, ah1, ah2, ah3, bl2, bl3);
                mma16816(acc[1][2*j][0], acc[1][2*j][1], acc[1][2*j][2], acc[1][2*j][3],
                         ag0, ag1, ag2, ag3, bl0, bl1);
                mma16816(acc[1][2*j+1][0], acc[1][2*j+1][1], acc[1][2*j+1][2], acc[1][2*j+1][3],
                         ag0, ag1, ag2, ag3, bl2, bl3);
            }
        }
    }

    // ---- epilogue -----------------------------------------------------------
    const float s2 = 0.70710678118654752f;
    const float* bb = bias + (size_t)e * NDIM;
#pragma unroll
    for (int mi = 0; mi < 2; mi++) {
#pragma unroll
        for (int h = 0; h < 2; h++) {
            int row = row0 + wm * 32 + mi * 16 + (l >> 2) + h * 8;
            if (row >= nrows) continue;
            int tok = 0; float gt = 0.f;
            if (MODE == 1) {
                tok = g_rows[e * CAP + row];
                gt  = g_gslot[e * CAP + row];
            }
#pragma unroll
            for (int nj = 0; nj < 6; nj++) {
                int coln = col0 + wn * 48 + nj * 8 + (l & 3) * 2;
                float v0 = acc[mi][nj][h * 2 + 0] + bb[coln];
                float v1 = acc[mi][nj][h * 2 + 1] + bb[coln + 1];
                if (MODE == 0) {
                    v0 = 0.5f * v0 * (1.0f + erff(v0 * s2));
                    v1 = 0.5f * v1 * (1.0f + erff(v1 * s2));
                    size_t idx = (size_t)(e * CAP + row) * HH + coln;
                    *reinterpret_cast<uint32_t*>(&g_Hhi[idx]) = cvt2h(v0, v1);
                } else {
                    float* dst = out + (size_t)tok * DD + coln;
                    atomicAdd(dst,     gt * v0);
                    atomicAdd(dst + 1, gt * v1);
                }
            }
        }
    }
}

// ---------------- launch -----------------------------------------------------
extern "C" void kernel_launch(void* const* d_in, const int* in_sizes, int n_in,
                              void* d_out, int out_size) {
    (void)in_sizes; (void)n_in; (void)out_size;
    const float* x  = (const float*)d_in[0];
    const float* Wr = (const float*)d_in[1];
    const float* w1 = (const float*)d_in[2];
    const float* b1 = (const float*)d_in[3];
    const float* w2 = (const float*)d_in[4];
    const float* b2 = (const float*)d_in[5];
    float* out = (float*)d_out;

    cudaFuncSetAttribute(moe_gemm<0>, cudaFuncAttributeMaxDynamicSharedMemorySize, GEMM_SMEM);
    cudaFuncSetAttribute(moe_gemm<1>, cudaFuncAttributeMaxDynamicSharedMemorySize, GEMM_SMEM);

    cvt_x_kernel<<<(NTOK * DD / 4) / 256, 256>>>(x);
    zero_out_kernel<<<(NTOK * DD / 4) / 256, 256>>>(out);
    router_kernel<<<NTOK / 8, 256>>>(x, Wr);
    assign_kernel<<<1, ATH>>>();
    moe_gemm<0><<<dim3(HH / 96, CAP / 128, EE), 256, GEMM_SMEM>>>(w1, b1, nullptr);
    moe_gemm<1><<<dim3(DD / 96, CAP / 128, EE), 256, GEMM_SMEM>>>(w2, b2, out);
}